// round 4
// baseline (speedup 1.0000x reference)
#include <cuda_runtime.h>

// LePEAttention: out = Q (K^T V) * 2/sqrt(32); no softmax. 128 batches (t,b,win,head),
// each: Q,K,V = [32 ch][1568 pos], pos = 56 rows x 28 cols (win selects col half).

#define HW4    784                 // 3136/4
#define NB     128
#define SROW   29                  // row stride in float4 units (28 + 1 pad)
#define CH_F4  (32 * SROW)         // one tensor, one 4-row chunk: 928 f4
#define BUFF4  (2 * CH_F4)         // K+V chunk: 1856 f4 = 29696 B
#define NBUF   3
#define P1_SMEM (NBUF * BUFF4 * 16)
#define SCALE2 0.35355339059327373f

__device__ float g_part[NB * 2 * 1024];

#define FFMA2(d, a, b) \
    asm("fma.rn.f32x2 %0, %1, %2, %0;" : "+l"(d) : "l"(a), "l"(b))

__device__ __forceinline__ unsigned long long pack2(float x, float y) {
    unsigned long long r;
    asm("mov.b64 %0, {%1,%2};" : "=l"(r) : "f"(x), "f"(y));
    return r;
}
__device__ __forceinline__ float2 unpack2(unsigned long long a) {
    float2 f;
    asm("mov.b64 {%0,%1}, %2;" : "=f"(f.x), "=f"(f.y) : "l"(a));
    return f;
}
__device__ __forceinline__ void cp16(float4* dst, const float4* src) {
    unsigned d = (unsigned)__cvta_generic_to_shared(dst);
    asm volatile("cp.async.ca.shared.global [%0], [%1], 16;" :: "r"(d), "l"(src));
}

// ================= Pass 1: M = K^T V (per batch-half), 3-stage pipeline =================
__global__ __launch_bounds__(224, 2) void p1(const float* __restrict__ K,
                                             const float* __restrict__ V) {
    extern __shared__ float4 sm[];

    const int tid   = threadIdx.x;
    const int half  = blockIdx.x;       // rows [0,28) / [28,56)
    const int batch = blockIdx.y;
    const int h   = batch & 7;
    const int win = (batch >> 3) & 1;
    const int tb  = batch >> 4;
    const int base4 = (tb * 256 + h * 32) * HW4 + win * 7;

    const float4* Kp = (const float4*)K;
    const float4* Vp = (const float4*)V;

    // 8 load slots/thread/chunk; slots 0-3 = K, 4-7 = V (224*4 = 896 = 32ch*28f4)
    int sm_off[8], g_off[8];
    #pragma unroll
    for (int it = 0; it < 8; ++it) {
        int ii = tid + (it & 3) * 224;            // 0..895
        int ch = ii / 28;
        int u  = ii - ch * 28;
        int r  = u / 7;
        int cu = u - r * 7;
        sm_off[it] = (it >= 4 ? CH_F4 : 0) + ch * SROW + u;
        g_off[it]  = ch * HW4 + r * 14 + cu;
    }

    const int lane = tid & 31;
    const int warp = tid >> 5;          // 7 warps = 7 position groups
    const int d1g  = lane & 3;          // k-ch {d1g + 4i}
    const int d2g  = lane >> 2;         // v-ch {4*d2g + j}

    unsigned long long acc[8][4];
    #pragma unroll
    for (int i = 0; i < 8; i++)
        #pragma unroll
        for (int j = 0; j < 4; j++) acc[i][j] = 0ull;

    // prologue: chunks 0,1 (two groups in flight)
    #pragma unroll
    for (int pc = 0; pc < 2; ++pc) {
        const int rb = half * 28 + pc * 4;
        #pragma unroll
        for (int it = 0; it < 8; ++it)
            cp16(&sm[pc * BUFF4 + sm_off[it]],
                 (it >= 4 ? Vp : Kp) + base4 + g_off[it] + rb * 14);
        asm volatile("cp.async.commit_group;");
    }

    #pragma unroll 1
    for (int c = 0; c < 7; ++c) {
        // pending groups here = {c, c+1} (c<6) or {6}. Must retire chunk c
        // before reading it: leave <=1 pending (<=0 on the last chunk).
        if (c < 6) asm volatile("cp.async.wait_group 1;");
        else       asm volatile("cp.async.wait_group 0;");
        __syncthreads();   // also: all threads done reading buffer (c+2)%3 == (c-1)%3

        if (c + 2 < 7) {
            const int buf = (c + 2) % 3;
            const int rb  = half * 28 + (c + 2) * 4;
            #pragma unroll
            for (int it = 0; it < 8; ++it)
                cp16(&sm[buf * BUFF4 + sm_off[it]],
                     (it >= 4 ? Vp : Kp) + base4 + g_off[it] + rb * 14);
            asm volatile("cp.async.commit_group;");
        }

        const float4* sK = &sm[(c % 3) * BUFF4];
        const float4* sV = sK + CH_F4;
        #pragma unroll
        for (int qq = 0; qq < 4; ++qq) {
            const int p4 = warp * 4 + qq;
            ulonglong2 vf[4];
            #pragma unroll
            for (int j = 0; j < 4; j++)
                vf[j] = *reinterpret_cast<const ulonglong2*>(&sV[(4 * d2g + j) * SROW + p4]);
            #pragma unroll
            for (int i = 0; i < 8; i++) {
                ulonglong2 kf =
                    *reinterpret_cast<const ulonglong2*>(&sK[(d1g + 4 * i) * SROW + p4]);
                #pragma unroll
                for (int j = 0; j < 4; j++) {
                    FFMA2(acc[i][j], kf.x, vf[j].x);
                    FFMA2(acc[i][j], kf.y, vf[j].y);
                }
            }
        }
    }

    float res[8][4];
    #pragma unroll
    for (int i = 0; i < 8; i++)
        #pragma unroll
        for (int j = 0; j < 4; j++) {
            float2 f = unpack2(acc[i][j]);
            res[i][j] = f.x + f.y;
        }

    __syncthreads();                    // buffers free for reduction
    float* sRed = (float*)sm;           // 6*1024 floats = 24 KB
    if (warp) {
        #pragma unroll
        for (int i = 0; i < 8; i++)
            #pragma unroll
            for (int j = 0; j < 4; j++)
                sRed[(warp - 1) * 1024 + (d1g + 4 * i) * 32 + 4 * d2g + j] = res[i][j];
    }
    __syncthreads();
    if (!warp) {
        float* o = &g_part[((batch << 1) | half) << 10];
        #pragma unroll
        for (int i = 0; i < 8; i++)
            #pragma unroll
            for (int j = 0; j < 4; j++) {
                const int idx = (d1g + 4 * i) * 32 + 4 * d2g + j;
                float s = res[i][j];
                #pragma unroll
                for (int w = 0; w < 6; w++) s += sRed[w * 1024 + idx];
                o[idx] = s;
            }
    }
}

// ================= Pass 2: out = M^T q, thread = 4 pos x 8 ch_out =================
__global__ __launch_bounds__(224, 3) void p2(const float* __restrict__ Q,
                                             float* __restrict__ O) {
    __shared__ float sM[1024];
    const int tid   = threadIdx.x;
    const int batch = blockIdx.y;

    {
        const float* gp = &g_part[batch << 11];
        for (int i = tid; i < 1024; i += 224)
            sM[i] = (gp[i] + gp[1024 + i]) * SCALE2;
    }
    __syncthreads();

    const int h   = batch & 7;
    const int win = (batch >> 3) & 1;
    const int tb  = batch >> 4;

    const int cg  = tid & 3;                    // ch_out group: {cg*8 .. cg*8+7}
    const int gpq = blockIdx.x * 56 + (tid >> 2);  // 0..391 position quad
    const int r   = gpq / 7;
    const int c4  = gpq - r * 7;
    const int base4 = (tb * 256 + h * 32) * HW4 + r * 14 + win * 7 + c4;

    const float4* Q4 = (const float4*)Q;
    float4* O4 = (float4*)O;

    unsigned long long acc[4][4];               // [pos][ch_out pair]
    #pragma unroll
    for (int p = 0; p < 4; p++)
        #pragma unroll
        for (int j = 0; j < 4; j++) acc[p][j] = 0ull;

    #pragma unroll
    for (int chb = 0; chb < 4; ++chb) {
        float4 qv[8];
        #pragma unroll
        for (int d = 0; d < 8; d++) qv[d] = Q4[base4 + (chb * 8 + d) * HW4];
        #pragma unroll
        for (int d = 0; d < 8; d++) {
            const ulonglong2* mr =
                reinterpret_cast<const ulonglong2*>(&sM[(chb * 8 + d) * 32 + cg * 8]);
            ulonglong2 m0 = mr[0], m1 = mr[1];
            unsigned long long q0 = pack2(qv[d].x, qv[d].x);
            unsigned long long q1 = pack2(qv[d].y, qv[d].y);
            unsigned long long q2 = pack2(qv[d].z, qv[d].z);
            unsigned long long q3 = pack2(qv[d].w, qv[d].w);
            FFMA2(acc[0][0], q0, m0.x); FFMA2(acc[0][1], q0, m0.y);
            FFMA2(acc[0][2], q0, m1.x); FFMA2(acc[0][3], q0, m1.y);
            FFMA2(acc[1][0], q1, m0.x); FFMA2(acc[1][1], q1, m0.y);
            FFMA2(acc[1][2], q1, m1.x); FFMA2(acc[1][3], q1, m1.y);
            FFMA2(acc[2][0], q2, m0.x); FFMA2(acc[2][1], q2, m0.y);
            FFMA2(acc[2][2], q2, m1.x); FFMA2(acc[2][3], q2, m1.y);
            FFMA2(acc[3][0], q3, m0.x); FFMA2(acc[3][1], q3, m0.y);
            FFMA2(acc[3][2], q3, m1.x); FFMA2(acc[3][3], q3, m1.y);
        }
    }

    #pragma unroll
    for (int j = 0; j < 4; ++j) {
        float2 a0 = unpack2(acc[0][j]);
        float2 a1 = unpack2(acc[1][j]);
        float2 a2 = unpack2(acc[2][j]);
        float2 a3 = unpack2(acc[3][j]);
        float4 lo = make_float4(a0.x, a1.x, a2.x, a3.x);
        float4 hi = make_float4(a0.y, a1.y, a2.y, a3.y);
        O4[base4 + (cg * 8 + 2 * j)     * HW4] = lo;
        O4[base4 + (cg * 8 + 2 * j + 1) * HW4] = hi;
    }
}

extern "C" void kernel_launch(void* const* d_in, const int* in_sizes, int n_in,
                              void* d_out, int out_size) {
    const float* q = (const float*)d_in[0];
    const float* k = (const float*)d_in[1];
    const float* v = (const float*)d_in[2];
    float* o = (float*)d_out;

    cudaFuncSetAttribute(p1, cudaFuncAttributeMaxDynamicSharedMemorySize, P1_SMEM);
    p1<<<dim3(2, NB), 224, P1_SMEM>>>(k, v);
    p2<<<dim3(7, NB), 224>>>(q, o);
}